// round 15
// baseline (speedup 1.0000x reference)
#include <cuda_runtime.h>
#include <cuda_bf16.h>
#include <cuda_fp16.h>
#include <cuda_fp8.h>
#include <math.h>

#define NRAYS 4096
#define NS    256
#define RES   160
#define RES2  (RES*RES)
#define RES3  (RES*RES*RES)
#define TNEAR 0.05f
#define TFAR  2.0f
#define ACT_SHIFT (-13.8155095579f)
#define WEPS  1e-9f

// packed bf16x2 weight fragments: [n][kpair], low half = even k
__device__ unsigned int g_w0p[128 * 8];    // layer0 (feature part / 16)
__device__ unsigned int g_w1p[128 * 64];   // layer1
__device__ unsigned int g_w2p[8 * 64];     // layer2

// fp8 channel-interleaved feature grid: 16B record = 12 e4m3 (x16 scaled) + 4 pad
__device__ __align__(16) unsigned int g_pack[RES3 * 4];   // 65.5 MB

// ---- dynamic smem layout --------------------------------------------------
// [0, 34816)  w1s: 128 rows x 272B (256B data + 16B pad, ldmatrix conflict-free)
// then 2 per-ray blocks of PER_SZ bytes
#define W1S_OFF   0
#define PER_OFF   34816
#define OFF_H0     0        // 32*136 bf16 = 8704
#define OFF_XB     8704     // 32*24 bf16 = 1536
#define OFF_CORNER 10240    // 256 x 16B  = 4096
#define OFF_WGT    14336    // 256 f32    = 1024
#define OFF_VW     15360    // 128 f32    = 512
#define OFF_RGB    15872    // 96 f32     = 384
#define OFF_VEMB   16256    // 27 f32     = 108 (+pad)
#define OFF_WTOT   16368    // 4 f32
#define OFF_ANY    16384    // 8 int
#define OFF_LIST   16416    // 8 int
#define OFF_NACT   16448    // int
#define OFF_ACC    16452    // 3 f32
#define OFF_AINV   16464    // f32 (+pad)
#define PER_SZ     16480
#define SMEM_TOTAL (PER_OFF + 2 * PER_SZ)   // 67776 B

__device__ __forceinline__ unsigned int packbf2(float lo, float hi) {
    __nv_bfloat162 h = __floats2bfloat162_rn(lo, hi);
    return *reinterpret_cast<unsigned int*>(&h);
}

__global__ void prep_kernel(const float* __restrict__ w0,
                            const float* __restrict__ w1,
                            const float* __restrict__ w2)
{
    int i = blockIdx.x * 256 + threadIdx.x;
    if (i < 128 * 64) {
        int n = i >> 6, p = i & 63;
        g_w1p[i] = packbf2(w1[(2 * p) * 128 + n], w1[(2 * p + 1) * 128 + n]);
    }
    if (i < 128 * 8) {             // w0 feature rows carry the 1/16 descale
        int n = i >> 3, p = i & 7;
        int k0 = 2 * p, k1 = 2 * p + 1;
        float lo = (k0 < 12) ? w0[k0 * 128 + n] * 0.0625f : 0.0f;
        float hi = (k1 < 12) ? w0[k1 * 128 + n] * 0.0625f : 0.0f;
        g_w0p[i] = packbf2(lo, hi);
    }
    if (i < 8 * 64) {
        int n = i >> 6, p = i & 63;
        float lo = (n < 3) ? w2[(2 * p) * 3 + n] : 0.0f;
        float hi = (n < 3) ? w2[(2 * p + 1) * 3 + n] : 0.0f;
        g_w2p[i] = packbf2(lo, hi);
    }
}

// [12][RES3] fp32 -> [RES3] 16B fp8 records (value*16, e4m3)
__global__ void relayout_kernel(const float* __restrict__ feat)
{
    int v = blockIdx.x * 256 + threadIdx.x;
    if (v >= RES3) return;
    unsigned int r[3];
    #pragma unroll
    for (int p = 0; p < 3; p++) {
        unsigned int w = 0;
        #pragma unroll
        for (int j = 0; j < 4; j++) {
            int c = 4 * p + j;
            unsigned int b = (unsigned int)__nv_cvt_float_to_fp8(
                feat[c * RES3 + v] * 16.0f, __NV_SATFINITE, __NV_E4M3);
            w |= b << (8 * j);
        }
        r[p] = w;
    }
    reinterpret_cast<uint4*>(g_pack)[v] = make_uint4(r[0], r[1], r[2], 0u);
}

#define LDSM4(A0,A1,A2,A3,addr) \
    asm volatile("ldmatrix.sync.aligned.m8n8.x4.shared.b16 {%0,%1,%2,%3}, [%4];" \
        : "=r"(A0), "=r"(A1), "=r"(A2), "=r"(A3) : "r"(addr))

#define MMA_BF16(C,A0,A1,A2,A3,B0r,B1r) \
    asm volatile("mma.sync.aligned.m16n8k16.row.col.f32.bf16.bf16.f32 " \
        "{%0,%1,%2,%3}, {%4,%5,%6,%7}, {%8,%9}, {%0,%1,%2,%3};" \
        : "+f"((C)[0]), "+f"((C)[1]), "+f"((C)[2]), "+f"((C)[3]) \
        : "r"(A0), "r"(A1), "r"(A2), "r"(A3), "r"(B0r), "r"(B1r))

#define CP_ASYNC16(dst, src) \
    asm volatile("cp.async.cg.shared.global [%0], [%1], 16;" \
        :: "r"(dst), "l"(src))
#define CP_COMMIT() asm volatile("cp.async.commit_group;")
#define BARG(id) asm volatile("bar.sync %0, 128;" :: "r"(id) : "memory")

__device__ __forceinline__ void tri_setup(float px, float py, float pz,
                                          int& base, float& fx, float& fy, float& fz)
{
    float ix = fminf(fmaxf((px + 1.0f) * 79.5f, 0.0f), 159.0f);
    float iy = fminf(fmaxf((py + 1.0f) * 79.5f, 0.0f), 159.0f);
    float iz = fminf(fmaxf((pz + 1.0f) * 79.5f, 0.0f), 159.0f);
    int x0 = min((int)ix, 158);
    int y0 = min((int)iy, 158);
    int z0 = min((int)iz, 158);
    fx = ix - (float)x0;
    fy = iy - (float)y0;
    fz = iz - (float)z0;
    base = x0 * RES2 + y0 * RES + z0;
}

__device__ __forceinline__ float tri_fetch(const float* __restrict__ g, int base,
                                           float fx, float fy, float fz)
{
    float c000 = g[base];
    float c001 = g[base + 1];
    float c010 = g[base + RES];
    float c011 = g[base + RES + 1];
    const float* g1 = g + base + RES2;
    float c100 = g1[0];
    float c101 = g1[1];
    float c110 = g1[RES];
    float c111 = g1[RES + 1];
    float gz = 1.0f - fz;
    float c00 = c000 * gz + c001 * fz;
    float c01 = c010 * gz + c011 * fz;
    float c10 = c100 * gz + c101 * fz;
    float c11 = c110 * gz + c111 * fz;
    float gy = 1.0f - fy;
    float c0 = c00 * gy + c01 * fy;
    float c1 = c10 * gy + c11 * fy;
    return c0 * (1.0f - fx) + c1 * fx;
}

__device__ __forceinline__ float sigm(float x) { return 1.0f / (1.0f + __expf(-x)); }

// issue cp.async for the two corner records of this thread for one tile
__device__ __forceinline__ void fetch_tile_async(
    int s0, int css, int c3, int dx, int dy, int dz,
    float ox, float oy, float oz, float vx, float vy, float vz, float tstep,
    unsigned int cbuf, float& w0v, float& w1v)
{
    #pragma unroll
    for (int p = 0; p < 2; p++) {
        int ss = css + p * 16;
        float t = TNEAR + (float)(s0 + ss) * tstep;
        float px = ox + vx * t, py = oy + vy * t, pz = oz + vz * t;
        int base; float fx, fy, fz;
        tri_setup(px, py, pz, base, fx, fy, fz);
        float w = (dx ? fx : 1.0f - fx) * (dy ? fy : 1.0f - fy) * (dz ? fz : 1.0f - fz);
        const unsigned int* src = g_pack +
            (size_t)(base + dx * RES2 + dy * RES + dz) * 4;
        unsigned int dst = cbuf + (unsigned int)(ss * 8 + c3) * 16;
        CP_ASYNC16(dst, src);
        if (p == 0) w0v = w; else w1v = w;
    }
}

// half2 weighted shfl-reduce over 8 corner lanes; lane c3==0 stores sample row
__device__ __forceinline__ void reduce_store_h2(
    const uint4* rec_p, float w, int row, int c3, __nv_bfloat16* s_xb)
{
    uint4 rec = *rec_p;
    unsigned int wd[3] = {rec.x, rec.y, rec.z};
    __half2 h[6];
    #pragma unroll
    for (int p = 0; p < 3; p++) {
        __half2_raw lo = __nv_cvt_fp8x2_to_halfraw2(
            (__nv_fp8x2_storage_t)(wd[p] & 0xFFFFu), __NV_E4M3);
        __half2_raw hi = __nv_cvt_fp8x2_to_halfraw2(
            (__nv_fp8x2_storage_t)(wd[p] >> 16), __NV_E4M3);
        h[2 * p]     = *reinterpret_cast<__half2*>(&lo);
        h[2 * p + 1] = *reinterpret_cast<__half2*>(&hi);
    }
    __half2 wh = __float2half2_rn(w);
    #pragma unroll
    for (int j = 0; j < 6; j++) h[j] = __hmul2(h[j], wh);
    #pragma unroll
    for (int r = 4; r >= 1; r >>= 1) {
        #pragma unroll
        for (int j = 0; j < 6; j++) {
            unsigned int v = __shfl_xor_sync(0xffffffffu,
                *reinterpret_cast<unsigned int*>(&h[j]), r);
            h[j] = __hadd2(h[j], *reinterpret_cast<__half2*>(&v));
        }
    }
    if (c3 == 0) {
        unsigned int o[8];
        #pragma unroll
        for (int j = 0; j < 6; j++) {
            float2 f2 = __half22float2(h[j]);
            o[j] = packbf2(f2.x, f2.y);
        }
        o[6] = 0u; o[7] = 0u;
        uint4* dst = reinterpret_cast<uint4*>(&s_xb[row * 24]);
        dst[0] = make_uint4(o[0], o[1], o[2], o[3]);
        dst[1] = make_uint4(o[4], o[5], o[6], o[7]);
    }
}

// --- main fused kernel: 2 rays per block (256 threads) ---------------------
__global__ __launch_bounds__(256, 3)
void dvgo_kernel(const float* __restrict__ rays_o, const float* __restrict__ rays_d,
                 const float* __restrict__ dens,  const float* __restrict__ feat,
                 const float* __restrict__ w0,    const float* __restrict__ b0,
                 const float* __restrict__ w1,    const float* __restrict__ b1,
                 const float* __restrict__ w2,    const float* __restrict__ b2,
                 float* __restrict__ out)
{
    extern __shared__ __align__(16) char smem[];
    const int tid  = threadIdx.x;
    const int rg   = tid >> 7;           // ray group 0/1
    const int rtid = tid & 127;          // thread within group
    const int wid  = rtid >> 5;          // warp within group 0..3
    const int lane = tid & 31;
    const int gq = lane >> 2;
    const int tq = lane & 3;
    const int ray = blockIdx.x * 2 + rg;

    char* gb = smem + PER_OFF + rg * PER_SZ;
    __nv_bfloat16* s_h0  = (__nv_bfloat16*)(gb + OFF_H0);
    __nv_bfloat16* s_xb  = (__nv_bfloat16*)(gb + OFF_XB);
    float* s_wgt  = (float*)(gb + OFF_WGT);
    float* s_vw   = (float*)(gb + OFF_VW);
    float* s_rgb  = (float*)(gb + OFF_RGB);
    float* s_vemb = (float*)(gb + OFF_VEMB);
    float* s_wtot = (float*)(gb + OFF_WTOT);
    int*   s_any  = (int*)(gb + OFF_ANY);
    int*   s_list = (int*)(gb + OFF_LIST);
    int*   s_nact = (int*)(gb + OFF_NACT);
    float* s_acc  = (float*)(gb + OFF_ACC);
    float* s_ainv = (float*)(gb + OFF_AINV);

    // cooperative w1 smem copy (whole block): 128 rows x 16 chunks of 16B
    {
        char* w1s = smem + W1S_OFF;
        for (int idx = tid; idx < 2048; idx += 256) {
            int n = idx >> 4, c = idx & 15;
            *reinterpret_cast<uint4*>(w1s + n * 272 + c * 16) =
                *reinterpret_cast<const uint4*>(g_w1p + n * 64 + c * 4);
        }
    }

    const float ox = rays_o[ray * 3 + 0];
    const float oy = rays_o[ray * 3 + 1];
    const float oz = rays_o[ray * 3 + 2];
    float rdx = rays_d[ray * 3 + 0];
    float rdy = rays_d[ray * 3 + 1];
    float rdz = rays_d[ray * 3 + 2];
    const float invn = rsqrtf(rdx * rdx + rdy * rdy + rdz * rdz);
    const float vx = rdx * invn, vy = rdy * invn, vz = rdz * invn;

    // view embedding (per group)
    if (rtid < 27) {
        float val;
        if (rtid < 3) {
            val = (rtid == 0) ? vx : ((rtid == 1) ? vy : vz);
        } else if (rtid < 15) {
            int k = rtid - 3;
            int d = k >> 2, f = k & 3;
            float v = (d == 0) ? vx : ((d == 1) ? vy : vz);
            val = sinf(v * (float)(1 << f));
        } else {
            int k = rtid - 15;
            int d = k >> 2, f = k & 3;
            float v = (d == 0) ? vx : ((d == 1) ? vy : vz);
            val = cosf(v * (float)(1 << f));
        }
        s_vemb[rtid] = val;
    }
    if (rtid < 3) s_acc[rtid] = 0.0f;
    if (rtid < 8) s_any[rtid] = 0;
    __syncthreads();

    // fold view embedding through w0 (fp32): neuron n = rtid
    {
        float vw = b0[rtid];
        #pragma unroll
        for (int k = 0; k < 27; k++) vw += s_vemb[k] * w0[(12 + k) * 128 + rtid];
        s_vw[rtid] = vw;
    }

    // ---- alpha for 2 consecutive samples per thread ----------------------
    const float tstep = (TFAR - TNEAR) / 255.0f;
    float a0, a1;
    #pragma unroll
    for (int p = 0; p < 2; p++) {
        int s = 2 * rtid + p;
        float t = TNEAR + (float)s * tstep;
        float px = ox + vx * t, py = oy + vy * t, pz = oz + vz * t;
        bool inbox = (px >= -1.0f) & (px <= 1.0f) &
                     (py >= -1.0f) & (py <= 1.0f) &
                     (pz >= -1.0f) & (pz <= 1.0f);
        float alpha = 0.0f;
        if (inbox) {
            int base; float fx, fy, fz;
            tri_setup(px, py, pz, base, fx, fy, fz);
            float d = tri_fetch(dens, base, fx, fy, fz);
            float e = expf(d + ACT_SHIFT);
            alpha = -expm1f(-0.5f * log1pf(e));
        }
        if (p == 0) a0 = alpha; else a1 = alpha;
    }

    // ---- parallel transmittance scan (per group) -------------------------
    const float m0 = 1.0f - a0, m1 = 1.0f - a1;
    float sc = m0 * m1;
    #pragma unroll
    for (int off = 1; off < 32; off <<= 1) {
        float v = __shfl_up_sync(0xffffffffu, sc, off);
        if (lane >= off) sc *= v;
    }
    float excl = __shfl_up_sync(0xffffffffu, sc, 1);
    if (lane == 0) excl = 1.0f;
    if (lane == 31) s_wtot[wid] = sc;
    __syncthreads();
    {
        float pre = 1.0f;
        #pragma unroll
        for (int w = 0; w < 4; w++) if (w < wid) pre *= s_wtot[w];
        float Te = pre * excl;
        float w0s = a0 * Te;
        float w1s = a1 * Te * m0;
        s_wgt[2 * rtid]     = w0s;
        s_wgt[2 * rtid + 1] = w1s;
        if ((w0s > WEPS) | (w1s > WEPS)) s_any[rtid >> 4] = 1;
        if (rtid == 0) *s_ainv = s_wtot[0] * s_wtot[1] * s_wtot[2] * s_wtot[3];
    }
    __syncthreads();
    if (rtid == 0) {
        int n = 0;
        #pragma unroll
        for (int tl = 0; tl < 8; tl++) if (s_any[tl]) s_list[n++] = tl;
        *s_nact = n;
    }

    // ---- small resident fragments (w0, w2, biases) -----------------------
    const int nbase = wid * 32;
    unsigned int B0f[4][2];
    #pragma unroll
    for (int nt = 0; nt < 4; nt++) {
        int n = nbase + nt * 8 + gq;
        B0f[nt][0] = g_w0p[n * 8 + tq];
        B0f[nt][1] = g_w0p[n * 8 + 4 + tq];
    }
    float b1lo[4], b1hi[4];
    #pragma unroll
    for (int nt = 0; nt < 4; nt++) {
        int c0 = nbase + nt * 8 + 2 * tq;
        b1lo[nt] = b1[c0];
        b1hi[nt] = b1[c0 + 1];
    }
    unsigned int W2[2][2];
    #pragma unroll
    for (int j = 0; j < 2; j++) {
        W2[j][0] = g_w2p[gq * 64 + (wid * 2 + j) * 8 + tq];
        W2[j][1] = g_w2p[gq * 64 + (wid * 2 + j) * 8 + 4 + tq];
    }
    const float biasr = (rtid < 96) ? b2[rtid % 3] : 0.0f;

    // addresses
    const unsigned int xb_base = (unsigned int)__cvta_generic_to_shared(s_xb);
    const unsigned int h0_base = (unsigned int)__cvta_generic_to_shared(s_h0);
    const unsigned int cn_base = (unsigned int)__cvta_generic_to_shared(gb + OFF_CORNER);
    const unsigned int w1_base = (unsigned int)__cvta_generic_to_shared(smem + W1S_OFF);
    const int lrow = (((lane >> 3) & 1) << 3) + (lane & 7);
    const int lch  = (lane >> 4) & 1;
    // B-ldmatrix lane row address: matrices [nt_lo,h0],[nt_lo,h1],[nt_hi,h0],[nt_hi,h1]
    const int bmi = lane >> 3, brr = lane & 7;
    const unsigned int brow0 = w1_base +
        (unsigned int)((nbase + (bmi >> 1) * 8 + brr) * 272 + (bmi & 1) * 16);

    // gather identity: 8 threads per sample
    const int g_css = rtid >> 3;
    const int g_c3 = rtid & 7;
    const int g_dz = g_c3 & 1;
    const int g_dy = (g_c3 >> 1) & 1;
    const int g_dx = (g_c3 >> 2) & 1;

    const int barid = rg + 1;
    float racc = 0.0f;

    __syncthreads();          // w1s + all per-ray prologue data ready
    const int nact = *s_nact;

    float cw0, cw1, nw0, nw1;
    if (nact > 0) {
        fetch_tile_async(s_list[0] * 32, g_css, g_c3, g_dx, g_dy, g_dz,
                         ox, oy, oz, vx, vy, vz, tstep, cn_base, cw0, cw1);
        CP_COMMIT();
    }

    for (int i = 0; i < nact; i++) {
        const int s0 = s_list[i] * 32;

        asm volatile("cp.async.wait_group 0;");
        // each thread reduces the records it fetched itself (own slots)
        reduce_store_h2((const uint4*)(gb + OFF_CORNER) + (g_css * 8 + g_c3),
                        cw0, g_css,      g_c3, s_xb);
        reduce_store_h2((const uint4*)(gb + OFF_CORNER) + ((g_css + 16) * 8 + g_c3),
                        cw1, g_css + 16, g_c3, s_xb);
        // prefetch next tile into the same (already-consumed) slots
        if (i + 1 < nact) {
            fetch_tile_async(s_list[i + 1] * 32, g_css, g_c3, g_dx, g_dy, g_dz,
                             ox, oy, oz, vx, vy, vz, tstep, cn_base, nw0, nw1);
            CP_COMMIT();
        }
        BARG(barid);                                       // A: xb ready

        // seed rgb accumulator; layer 0
        if (rtid < 96) s_rgb[rtid] = biasr;
        #pragma unroll
        for (int mh = 0; mh < 2; mh++) {
            unsigned int a0r, a1r, a2r, a3r;
            LDSM4(a0r, a1r, a2r, a3r, xb_base + (mh * 16 + lrow) * 48 + lch * 16);
            #pragma unroll
            for (int nt = 0; nt < 4; nt++) {
                float C0[4] = {0.0f, 0.0f, 0.0f, 0.0f};
                MMA_BF16(C0, a0r, a1r, a2r, a3r, B0f[nt][0], B0f[nt][1]);
                int cc = nbase + nt * 8 + 2 * tq;
                float v0 = s_vw[cc], v1 = s_vw[cc + 1];
                unsigned int wlo = packbf2(fmaxf(C0[0] + v0, 0.0f),
                                           fmaxf(C0[1] + v1, 0.0f));
                unsigned int whi = packbf2(fmaxf(C0[2] + v0, 0.0f),
                                           fmaxf(C0[3] + v1, 0.0f));
                *reinterpret_cast<unsigned int*>(&s_h0[(mh * 16 + gq) * 136 + cc]) = wlo;
                *reinterpret_cast<unsigned int*>(&s_h0[(mh * 16 + 8 + gq) * 136 + cc]) = whi;
            }
        }
        BARG(barid);                                       // B: h0 ready

        // layer 1: B fragments from w1 smem via ldmatrix
        float C1[2][4][4];
        #pragma unroll
        for (int mh = 0; mh < 2; mh++)
            #pragma unroll
            for (int nt = 0; nt < 4; nt++) {
                C1[mh][nt][0] = b1lo[nt]; C1[mh][nt][1] = b1hi[nt];
                C1[mh][nt][2] = b1lo[nt]; C1[mh][nt][3] = b1hi[nt];
            }
        #pragma unroll
        for (int ks = 0; ks < 8; ks++) {
            unsigned int bf0, bf1, bf2, bf3, bf4, bf5, bf6, bf7;
            LDSM4(bf0, bf1, bf2, bf3, brow0 + ks * 32);
            LDSM4(bf4, bf5, bf6, bf7, brow0 + 16 * 272 + ks * 32);
            #pragma unroll
            for (int mh = 0; mh < 2; mh++) {
                unsigned int h0r, h1r, h2r, h3r;
                LDSM4(h0r, h1r, h2r, h3r,
                      h0_base + (mh * 16 + lrow) * 272 + ks * 32 + lch * 16);
                MMA_BF16(C1[mh][0], h0r, h1r, h2r, h3r, bf0, bf1);
                MMA_BF16(C1[mh][1], h0r, h1r, h2r, h3r, bf2, bf3);
                MMA_BF16(C1[mh][2], h0r, h1r, h2r, h3r, bf4, bf5);
                MMA_BF16(C1[mh][3], h0r, h1r, h2r, h3r, bf6, bf7);
            }
        }
        // relu + repack C1 as layer-2 A fragments; partial L2 product
        #pragma unroll
        for (int mh = 0; mh < 2; mh++) {
            float C2[4] = {0.0f, 0.0f, 0.0f, 0.0f};
            #pragma unroll
            for (int j = 0; j < 2; j++) {
                unsigned int a0p = packbf2(fmaxf(C1[mh][2*j][0], 0.0f), fmaxf(C1[mh][2*j][1], 0.0f));
                unsigned int a1p = packbf2(fmaxf(C1[mh][2*j][2], 0.0f), fmaxf(C1[mh][2*j][3], 0.0f));
                unsigned int a2p = packbf2(fmaxf(C1[mh][2*j+1][0], 0.0f), fmaxf(C1[mh][2*j+1][1], 0.0f));
                unsigned int a3p = packbf2(fmaxf(C1[mh][2*j+1][2], 0.0f), fmaxf(C1[mh][2*j+1][3], 0.0f));
                MMA_BF16(C2, a0p, a1p, a2p, a3p, W2[j][0], W2[j][1]);
            }
            int r0 = (mh * 16 + gq) * 3, r1 = (mh * 16 + 8 + gq) * 3;
            int c0 = 2 * tq;
            if (c0 < 3) {
                atomicAdd(&s_rgb[r0 + c0], C2[0]);
                atomicAdd(&s_rgb[r1 + c0], C2[2]);
            }
            if (c0 + 1 < 3) {
                atomicAdd(&s_rgb[r0 + c0 + 1], C2[1]);
                atomicAdd(&s_rgb[r1 + c0 + 1], C2[3]);
            }
        }
        BARG(barid);                                       // C: rgb ready

        // sigmoid + weighted accumulate (96 threads: sample rtid/3, ch rtid%3)
        if (rtid < 96) racc += s_wgt[s0 + rtid / 3] * sigm(s_rgb[rtid]);

        cw0 = nw0; cw1 = nw1;
    }

    if (rtid < 96) atomicAdd(&s_acc[rtid % 3], racc);
    BARG(barid);
    if (rtid < 3) out[ray * 3 + rtid] = s_acc[rtid] + *s_ainv;
}

extern "C" void kernel_launch(void* const* d_in, const int* in_sizes, int n_in,
                              void* d_out, int out_size)
{
    const float* rays_o = (const float*)d_in[0];
    const float* rays_d = (const float*)d_in[1];
    const float* dens   = (const float*)d_in[2];
    const float* feat   = (const float*)d_in[3];
    const float* w0     = (const float*)d_in[4];
    const float* b0     = (const float*)d_in[5];
    const float* w1     = (const float*)d_in[6];
    const float* b1     = (const float*)d_in[7];
    const float* w2     = (const float*)d_in[8];
    const float* b2     = (const float*)d_in[9];
    float* out = (float*)d_out;

    cudaFuncSetAttribute(dvgo_kernel,
                         cudaFuncAttributeMaxDynamicSharedMemorySize, SMEM_TOTAL);
    prep_kernel<<<32, 256>>>(w0, w1, w2);
    relayout_kernel<<<RES3 / 256, 256>>>(feat);
    dvgo_kernel<<<NRAYS / 2, 256, SMEM_TOTAL>>>(rays_o, rays_d, dens, feat,
                                                w0, b0, w1, b1, w2, b2, out);
}

// round 17
// speedup vs baseline: 1.2340x; 1.2340x over previous
#include <cuda_runtime.h>
#include <cuda_bf16.h>
#include <cuda_fp16.h>
#include <cuda_fp8.h>
#include <math.h>

#define NRAYS 4096
#define NS    256
#define RES   160
#define RES2  (RES*RES)
#define RES3  (RES*RES*RES)
#define TNEAR 0.05f
#define TFAR  2.0f
#define ACT_SHIFT (-13.8155095579f)
#define WEPS  1e-9f

// packed bf16x2 weight fragments: [n][kpair], low half = even k
__device__ unsigned int g_w0p[128 * 8];    // layer0 (feature part / 16)
__device__ unsigned int g_w1p[128 * 64];   // layer1
__device__ unsigned int g_w2p[8 * 64];     // layer2

// fp8 channel-interleaved feature grid: 16B record = 12 e4m3 (x16 scaled) + 4 pad
__device__ __align__(16) unsigned int g_pack[RES3 * 4];   // 65.5 MB

__device__ __forceinline__ unsigned int packbf2(float lo, float hi) {
    __nv_bfloat162 h = __floats2bfloat162_rn(lo, hi);
    return *reinterpret_cast<unsigned int*>(&h);
}

__global__ void prep_kernel(const float* __restrict__ w0,
                            const float* __restrict__ w1,
                            const float* __restrict__ w2)
{
    int i = blockIdx.x * 256 + threadIdx.x;
    if (i < 128 * 64) {
        int n = i >> 6, p = i & 63;
        g_w1p[i] = packbf2(w1[(2 * p) * 128 + n], w1[(2 * p + 1) * 128 + n]);
    }
    if (i < 128 * 8) {             // w0 feature rows carry the 1/16 descale
        int n = i >> 3, p = i & 7;
        int k0 = 2 * p, k1 = 2 * p + 1;
        float lo = (k0 < 12) ? w0[k0 * 128 + n] * 0.0625f : 0.0f;
        float hi = (k1 < 12) ? w0[k1 * 128 + n] * 0.0625f : 0.0f;
        g_w0p[i] = packbf2(lo, hi);
    }
    if (i < 8 * 64) {
        int n = i >> 6, p = i & 63;
        float lo = (n < 3) ? w2[(2 * p) * 3 + n] : 0.0f;
        float hi = (n < 3) ? w2[(2 * p + 1) * 3 + n] : 0.0f;
        g_w2p[i] = packbf2(lo, hi);
    }
}

// [12][RES3] fp32 -> [RES3] 16B fp8 records (value*16, e4m3)
__global__ void relayout_kernel(const float* __restrict__ feat)
{
    int v = blockIdx.x * 256 + threadIdx.x;
    if (v >= RES3) return;
    unsigned int r[3];
    #pragma unroll
    for (int p = 0; p < 3; p++) {
        unsigned int w = 0;
        #pragma unroll
        for (int j = 0; j < 4; j++) {
            int c = 4 * p + j;
            unsigned int b = (unsigned int)__nv_cvt_float_to_fp8(
                feat[c * RES3 + v] * 16.0f, __NV_SATFINITE, __NV_E4M3);
            w |= b << (8 * j);
        }
        r[p] = w;
    }
    reinterpret_cast<uint4*>(g_pack)[v] = make_uint4(r[0], r[1], r[2], 0u);
}

#define LDSM4(A0,A1,A2,A3,addr) \
    asm volatile("ldmatrix.sync.aligned.m8n8.x4.shared.b16 {%0,%1,%2,%3}, [%4];" \
        : "=r"(A0), "=r"(A1), "=r"(A2), "=r"(A3) : "r"(addr))

#define MMA_BF16(C,A0,A1,A2,A3,B0r,B1r) \
    asm volatile("mma.sync.aligned.m16n8k16.row.col.f32.bf16.bf16.f32 " \
        "{%0,%1,%2,%3}, {%4,%5,%6,%7}, {%8,%9}, {%0,%1,%2,%3};" \
        : "+f"((C)[0]), "+f"((C)[1]), "+f"((C)[2]), "+f"((C)[3]) \
        : "r"(A0), "r"(A1), "r"(A2), "r"(A3), "r"(B0r), "r"(B1r))

#define CP_ASYNC16(dst, src) \
    asm volatile("cp.async.cg.shared.global [%0], [%1], 16;" \
        :: "r"(dst), "l"(src))
#define CP_COMMIT() asm volatile("cp.async.commit_group;")

__device__ __forceinline__ void tri_setup(float px, float py, float pz,
                                          int& base, float& fx, float& fy, float& fz)
{
    float ix = fminf(fmaxf((px + 1.0f) * 79.5f, 0.0f), 159.0f);
    float iy = fminf(fmaxf((py + 1.0f) * 79.5f, 0.0f), 159.0f);
    float iz = fminf(fmaxf((pz + 1.0f) * 79.5f, 0.0f), 159.0f);
    int x0 = min((int)ix, 158);
    int y0 = min((int)iy, 158);
    int z0 = min((int)iz, 158);
    fx = ix - (float)x0;
    fy = iy - (float)y0;
    fz = iz - (float)z0;
    base = x0 * RES2 + y0 * RES + z0;
}

__device__ __forceinline__ float tri_fetch(const float* __restrict__ g, int base,
                                           float fx, float fy, float fz)
{
    float c000 = g[base];
    float c001 = g[base + 1];
    float c010 = g[base + RES];
    float c011 = g[base + RES + 1];
    const float* g1 = g + base + RES2;
    float c100 = g1[0];
    float c101 = g1[1];
    float c110 = g1[RES];
    float c111 = g1[RES + 1];
    float gz = 1.0f - fz;
    float c00 = c000 * gz + c001 * fz;
    float c01 = c010 * gz + c011 * fz;
    float c10 = c100 * gz + c101 * fz;
    float c11 = c110 * gz + c111 * fz;
    float gy = 1.0f - fy;
    float c0 = c00 * gy + c01 * fy;
    float c1 = c10 * gy + c11 * fy;
    return c0 * (1.0f - fx) + c1 * fx;
}

__device__ __forceinline__ float sigm(float x) { return 1.0f / (1.0f + __expf(-x)); }

// issue cp.async for the two corner records of this thread for one tile
__device__ __forceinline__ void fetch_tile_async(
    int s0, int css, int c3, int dx, int dy, int dz,
    float ox, float oy, float oz, float vx, float vy, float vz, float tstep,
    unsigned int cbuf, float& w0v, float& w1v)
{
    #pragma unroll
    for (int p = 0; p < 2; p++) {
        int ss = css + p * 16;
        float t = TNEAR + (float)(s0 + ss) * tstep;
        float px = ox + vx * t, py = oy + vy * t, pz = oz + vz * t;
        int base; float fx, fy, fz;
        tri_setup(px, py, pz, base, fx, fy, fz);
        float w = (dx ? fx : 1.0f - fx) * (dy ? fy : 1.0f - fy) * (dz ? fz : 1.0f - fz);
        const unsigned int* src = g_pack +
            (size_t)(base + dx * RES2 + dy * RES + dz) * 4;
        unsigned int dst = cbuf + (unsigned int)(ss * 8 + c3) * 16;
        CP_ASYNC16(dst, src);
        if (p == 0) w0v = w; else w1v = w;
    }
}

// half2 weighted shfl-reduce over 8 corner lanes; lane c3==0 stores sample row
__device__ __forceinline__ void reduce_store_h2(
    const uint4* rec_p, float w, int row, int c3, __nv_bfloat16* s_xb)
{
    uint4 rec = *rec_p;
    unsigned int wd[3] = {rec.x, rec.y, rec.z};
    __half2 h[6];
    #pragma unroll
    for (int p = 0; p < 3; p++) {
        __half2_raw lo = __nv_cvt_fp8x2_to_halfraw2(
            (__nv_fp8x2_storage_t)(wd[p] & 0xFFFFu), __NV_E4M3);
        __half2_raw hi = __nv_cvt_fp8x2_to_halfraw2(
            (__nv_fp8x2_storage_t)(wd[p] >> 16), __NV_E4M3);
        h[2 * p]     = *reinterpret_cast<__half2*>(&lo);
        h[2 * p + 1] = *reinterpret_cast<__half2*>(&hi);
    }
    __half2 wh = __float2half2_rn(w);
    #pragma unroll
    for (int j = 0; j < 6; j++) h[j] = __hmul2(h[j], wh);
    #pragma unroll
    for (int r = 4; r >= 1; r >>= 1) {
        #pragma unroll
        for (int j = 0; j < 6; j++) {
            unsigned int v = __shfl_xor_sync(0xffffffffu,
                *reinterpret_cast<unsigned int*>(&h[j]), r);
            h[j] = __hadd2(h[j], *reinterpret_cast<__half2*>(&v));
        }
    }
    if (c3 == 0) {
        unsigned int o[8];
        #pragma unroll
        for (int j = 0; j < 6; j++) {
            float2 f2 = __half22float2(h[j]);
            o[j] = packbf2(f2.x, f2.y);
        }
        o[6] = 0u; o[7] = 0u;
        uint4* dst = reinterpret_cast<uint4*>(&s_xb[row * 24]);
        dst[0] = make_uint4(o[0], o[1], o[2], o[3]);
        dst[1] = make_uint4(o[4], o[5], o[6], o[7]);
    }
}

// --- main fused kernel: one block (128 threads) per ray --------------------
__global__ __launch_bounds__(128, 4)
void dvgo_kernel(const float* __restrict__ rays_o, const float* __restrict__ rays_d,
                 const float* __restrict__ dens,  const float* __restrict__ feat,
                 const float* __restrict__ w0,    const float* __restrict__ b0,
                 const float* __restrict__ w1,    const float* __restrict__ b1,
                 const float* __restrict__ w2,    const float* __restrict__ b2,
                 float* __restrict__ out)
{
    __shared__ __align__(16) __nv_bfloat16 s_h0[32 * 136];
    __shared__ __align__(16) __nv_bfloat16 s_xb[32 * 24];
    __shared__ __align__(16) uint4 s_corner[2][256];   // 2 x 4KB fp8 records
    __shared__ float s_rgbw[4 * 96];   // per-warp rgb partial banks (no atomics)
    __shared__ float s_vw[128];
    __shared__ float s_vemb[27];
    __shared__ float s_wgt[NS];
    __shared__ float s_wtot[4];
    __shared__ int   s_any[8];
    __shared__ int   s_list[8];
    __shared__ int   s_nact;
    __shared__ float s_acc[3];
    __shared__ float s_ainv;

    const int ray = blockIdx.x;
    const int tid = threadIdx.x;
    const int wid = tid >> 5;
    const int lane = tid & 31;
    const int gq = lane >> 2;
    const int tq = lane & 3;

    const float ox = rays_o[ray * 3 + 0];
    const float oy = rays_o[ray * 3 + 1];
    const float oz = rays_o[ray * 3 + 2];
    float rdx = rays_d[ray * 3 + 0];
    float rdy = rays_d[ray * 3 + 1];
    float rdz = rays_d[ray * 3 + 2];
    const float invn = rsqrtf(rdx * rdx + rdy * rdy + rdz * rdz);
    const float vx = rdx * invn, vy = rdy * invn, vz = rdz * invn;

    // view embedding
    if (tid < 27) {
        float val;
        if (tid < 3) {
            val = (tid == 0) ? vx : ((tid == 1) ? vy : vz);
        } else if (tid < 15) {
            int k = tid - 3;
            int d = k >> 2, f = k & 3;
            float v = (d == 0) ? vx : ((d == 1) ? vy : vz);
            val = sinf(v * (float)(1 << f));
        } else {
            int k = tid - 15;
            int d = k >> 2, f = k & 3;
            float v = (d == 0) ? vx : ((d == 1) ? vy : vz);
            val = cosf(v * (float)(1 << f));
        }
        s_vemb[tid] = val;
    }
    if (tid < 3) s_acc[tid] = 0.0f;
    if (tid < 8) s_any[tid] = 0;
    __syncthreads();

    // fold view embedding through w0 (fp32)
    {
        float vw = b0[tid];
        #pragma unroll
        for (int k = 0; k < 27; k++) vw += s_vemb[k] * w0[(12 + k) * 128 + tid];
        s_vw[tid] = vw;
    }

    // ---- alpha for 2 consecutive samples per thread ----------------------
    const float tstep = (TFAR - TNEAR) / 255.0f;
    float a0, a1;
    #pragma unroll
    for (int p = 0; p < 2; p++) {
        int s = 2 * tid + p;
        float t = TNEAR + (float)s * tstep;
        float px = ox + vx * t, py = oy + vy * t, pz = oz + vz * t;
        bool inbox = (px >= -1.0f) & (px <= 1.0f) &
                     (py >= -1.0f) & (py <= 1.0f) &
                     (pz >= -1.0f) & (pz <= 1.0f);
        float alpha = 0.0f;
        if (inbox) {
            int base; float fx, fy, fz;
            tri_setup(px, py, pz, base, fx, fy, fz);
            float d = tri_fetch(dens, base, fx, fy, fz);
            float e = expf(d + ACT_SHIFT);
            alpha = -expm1f(-0.5f * log1pf(e));
        }
        if (p == 0) a0 = alpha; else a1 = alpha;
    }

    // ---- parallel transmittance scan -------------------------------------
    const float m0 = 1.0f - a0, m1 = 1.0f - a1;
    float sc = m0 * m1;
    #pragma unroll
    for (int off = 1; off < 32; off <<= 1) {
        float v = __shfl_up_sync(0xffffffffu, sc, off);
        if (lane >= off) sc *= v;
    }
    float excl = __shfl_up_sync(0xffffffffu, sc, 1);
    if (lane == 0) excl = 1.0f;
    if (lane == 31) s_wtot[wid] = sc;
    __syncthreads();
    {
        float pre = 1.0f;
        #pragma unroll
        for (int w = 0; w < 4; w++) if (w < wid) pre *= s_wtot[w];
        float Te = pre * excl;
        float w0s = a0 * Te;
        float w1s = a1 * Te * m0;
        s_wgt[2 * tid]     = w0s;
        s_wgt[2 * tid + 1] = w1s;
        if ((w0s > WEPS) | (w1s > WEPS)) s_any[tid >> 4] = 1;
        if (tid == 0) s_ainv = s_wtot[0] * s_wtot[1] * s_wtot[2] * s_wtot[3];
    }
    __syncthreads();
    if (tid == 0) {
        int n = 0;
        #pragma unroll
        for (int tl = 0; tl < 8; tl++) if (s_any[tl]) s_list[n++] = tl;
        s_nact = n;
    }

    // ---- resident B fragments (w0, w1, w2) -------------------------------
    const int nbase = wid * 32;
    unsigned int B1[4][8][2];
    unsigned int B0f[4][2];
    #pragma unroll
    for (int nt = 0; nt < 4; nt++) {
        int n = nbase + nt * 8 + gq;
        #pragma unroll
        for (int ks = 0; ks < 8; ks++) {
            B1[nt][ks][0] = g_w1p[n * 64 + ks * 8 + tq];
            B1[nt][ks][1] = g_w1p[n * 64 + ks * 8 + 4 + tq];
        }
        B0f[nt][0] = g_w0p[n * 8 + tq];
        B0f[nt][1] = g_w0p[n * 8 + 4 + tq];
    }
    float b1lo[4], b1hi[4];
    #pragma unroll
    for (int nt = 0; nt < 4; nt++) {
        int c0 = nbase + nt * 8 + 2 * tq;
        b1lo[nt] = b1[c0];
        b1hi[nt] = b1[c0 + 1];
    }
    // w2 B-fragments for this warp's two k-blocks (ks = wid*2 + j)
    unsigned int W2[2][2];
    #pragma unroll
    for (int j = 0; j < 2; j++) {
        W2[j][0] = g_w2p[gq * 64 + (wid * 2 + j) * 8 + tq];
        W2[j][1] = g_w2p[gq * 64 + (wid * 2 + j) * 8 + 4 + tq];
    }
    // epilogue identity: sample e_s = tid/3, channel e_c = tid%3 (tid < 96)
    const int e_s = tid / 3;
    const int e_c = tid - 3 * e_s;
    const float biasr = (tid < 96) ? b2[e_c] : 0.0f;

    // addresses
    const unsigned int xb_base = (unsigned int)__cvta_generic_to_shared(s_xb);
    const unsigned int h0_base = (unsigned int)__cvta_generic_to_shared(s_h0);
    const unsigned int cn_base = (unsigned int)__cvta_generic_to_shared(s_corner);
    const int lrow = (((lane >> 3) & 1) << 3) + (lane & 7);
    const int lch  = (lane >> 4) & 1;

    // gather identity: 8 threads per sample
    const int g_css = tid >> 3;
    const int g_c3 = tid & 7;
    const int g_dz = g_c3 & 1;
    const int g_dy = (g_c3 >> 1) & 1;
    const int g_dx = (g_c3 >> 2) & 1;

    float racc = 0.0f;
    int prev_s0 = -1;          // deferred-epilogue tile

    __syncthreads();
    const int nact = s_nact;

    float cw0, cw1, nw0, nw1;
    if (nact > 0) {
        fetch_tile_async(s_list[0] * 32, g_css, g_c3, g_dx, g_dy, g_dz,
                         ox, oy, oz, vx, vy, vz, tstep, cn_base, cw0, cw1);
        CP_COMMIT();
    }

    for (int i = 0; i < nact; i++) {
        const int s0 = s_list[i] * 32;
        const int buf = i & 1;

        if (i + 1 < nact) {
            fetch_tile_async(s_list[i + 1] * 32, g_css, g_c3, g_dx, g_dy, g_dz,
                             ox, oy, oz, vx, vy, vz, tstep,
                             cn_base + ((i + 1) & 1) * 4096, nw0, nw1);
            CP_COMMIT();
            asm volatile("cp.async.wait_group 1;");
        } else {
            asm volatile("cp.async.wait_group 0;");
        }

        // each thread reduces the records it fetched itself
        reduce_store_h2(&s_corner[buf][g_css * 8 + g_c3],        cw0, g_css,      g_c3, s_xb);
        reduce_store_h2(&s_corner[buf][(g_css + 16) * 8 + g_c3], cw1, g_css + 16, g_c3, s_xb);
        __syncthreads();                                   // barrier A
        // (also orders previous tile's rgb-bank writes before the read below)

        // deferred epilogue for the PREVIOUS tile (banks complete as of barrier A)
        if (prev_s0 >= 0 && tid < 96) {
            float v = biasr + s_rgbw[e_s * 3 + e_c] + s_rgbw[96 + e_s * 3 + e_c]
                    + s_rgbw[192 + e_s * 3 + e_c] + s_rgbw[288 + e_s * 3 + e_c];
            racc += s_wgt[prev_s0 + e_s] * sigm(v);
        }

        // layer 0
        #pragma unroll
        for (int mh = 0; mh < 2; mh++) {
            unsigned int a0r, a1r, a2r, a3r;
            LDSM4(a0r, a1r, a2r, a3r, xb_base + (mh * 16 + lrow) * 48 + lch * 16);
            #pragma unroll
            for (int nt = 0; nt < 4; nt++) {
                float C0[4] = {0.0f, 0.0f, 0.0f, 0.0f};
                MMA_BF16(C0, a0r, a1r, a2r, a3r, B0f[nt][0], B0f[nt][1]);
                int cc = nbase + nt * 8 + 2 * tq;
                float v0 = s_vw[cc], v1 = s_vw[cc + 1];
                unsigned int wlo = packbf2(fmaxf(C0[0] + v0, 0.0f),
                                           fmaxf(C0[1] + v1, 0.0f));
                unsigned int whi = packbf2(fmaxf(C0[2] + v0, 0.0f),
                                           fmaxf(C0[3] + v1, 0.0f));
                *reinterpret_cast<unsigned int*>(&s_h0[(mh * 16 + gq) * 136 + cc]) = wlo;
                *reinterpret_cast<unsigned int*>(&s_h0[(mh * 16 + 8 + gq) * 136 + cc]) = whi;
            }
        }
        __syncthreads();                                   // barrier B
        // (also orders the epilogue's bank reads before this tile's bank writes)

        // layer 1 (B1 resident) + layer 2 partial from registers -> own bank
        #pragma unroll
        for (int mh = 0; mh < 2; mh++) {
            float C1[4][4];
            #pragma unroll
            for (int nt = 0; nt < 4; nt++) {
                C1[nt][0] = b1lo[nt]; C1[nt][1] = b1hi[nt];
                C1[nt][2] = b1lo[nt]; C1[nt][3] = b1hi[nt];
            }
            #pragma unroll
            for (int ks = 0; ks < 8; ks++) {
                unsigned int h0r, h1r, h2r, h3r;
                LDSM4(h0r, h1r, h2r, h3r,
                      h0_base + (mh * 16 + lrow) * 272 + ks * 32);
                #pragma unroll
                for (int nt = 0; nt < 4; nt++)
                    MMA_BF16(C1[nt], h0r, h1r, h2r, h3r, B1[nt][ks][0], B1[nt][ks][1]);
            }
            // relu + repack C1 directly as layer-2 A fragments
            float C2[4] = {0.0f, 0.0f, 0.0f, 0.0f};
            #pragma unroll
            for (int j = 0; j < 2; j++) {
                unsigned int a0p = packbf2(fmaxf(C1[2*j][0], 0.0f), fmaxf(C1[2*j][1], 0.0f));
                unsigned int a1p = packbf2(fmaxf(C1[2*j][2], 0.0f), fmaxf(C1[2*j][3], 0.0f));
                unsigned int a2p = packbf2(fmaxf(C1[2*j+1][0], 0.0f), fmaxf(C1[2*j+1][1], 0.0f));
                unsigned int a3p = packbf2(fmaxf(C1[2*j+1][2], 0.0f), fmaxf(C1[2*j+1][3], 0.0f));
                MMA_BF16(C2, a0p, a1p, a2p, a3p, W2[j][0], W2[j][1]);
            }
            // plain stores into this warp's bank (one writer per address)
            int r0 = (mh * 16 + gq) * 3, r1 = (mh * 16 + 8 + gq) * 3;
            int c0 = 2 * tq;
            float* bank = s_rgbw + wid * 96;
            if (c0 < 3) {
                bank[r0 + c0] = C2[0];
                bank[r1 + c0] = C2[2];
            }
            if (c0 + 1 < 3) {
                bank[r0 + c0 + 1] = C2[1];
                bank[r1 + c0 + 1] = C2[3];
            }
        }

        prev_s0 = s0;
        cw0 = nw0; cw1 = nw1;
    }

    // drain the final tile's epilogue
    __syncthreads();
    if (prev_s0 >= 0 && tid < 96) {
        float v = biasr + s_rgbw[e_s * 3 + e_c] + s_rgbw[96 + e_s * 3 + e_c]
                + s_rgbw[192 + e_s * 3 + e_c] + s_rgbw[288 + e_s * 3 + e_c];
        racc += s_wgt[prev_s0 + e_s] * sigm(v);
    }

    if (tid < 96) atomicAdd(&s_acc[e_c], racc);
    __syncthreads();
    if (tid < 3) out[ray * 3 + tid] = s_acc[tid] + s_ainv;
}

extern "C" void kernel_launch(void* const* d_in, const int* in_sizes, int n_in,
                              void* d_out, int out_size)
{
    const float* rays_o = (const float*)d_in[0];
    const float* rays_d = (const float*)d_in[1];
    const float* dens   = (const float*)d_in[2];
    const float* feat   = (const float*)d_in[3];
    const float* w0     = (const float*)d_in[4];
    const float* b0     = (const float*)d_in[5];
    const float* w1     = (const float*)d_in[6];
    const float* b1     = (const float*)d_in[7];
    const float* w2     = (const float*)d_in[8];
    const float* b2     = (const float*)d_in[9];
    float* out = (float*)d_out;

    prep_kernel<<<32, 256>>>(w0, w1, w2);
    relayout_kernel<<<RES3 / 256, 256>>>(feat);
    dvgo_kernel<<<NRAYS, 128>>>(rays_o, rays_d, dens, feat,
                                w0, b0, w1, b1, w2, b2, out);
}